// round 1
// baseline (speedup 1.0000x reference)
#include <cuda_runtime.h>

// RandomShiftsAug == integer-shift gather with edge clamp.
// out[n,c,i,j] = x[n,c, clamp(i+sy-4,0,223), clamp(j+sx-4,0,223)]
// sx = shift[n,0,0,0], sy = shift[n,0,0,1], both in [0,8].

#define H 224
#define W 224
#define C 9
#define PAD 4
#define W4 (W / 4)                 // 56 float4 per row
#define PER_N (C * H * W4)         // 112896 float4 per image

__global__ __launch_bounds__(256) void shift_gather_kernel(
    const float* __restrict__ x,
    const int* __restrict__ shift,
    float* __restrict__ out)
{
    const int n = blockIdx.y;
    const int t = blockIdx.x * 256 + threadIdx.x;   // grid.x*256 == PER_N exactly

    const int j4   = t % W4;
    const int rest = t / W4;
    const int i    = rest % H;
    const int c    = rest / H;

    const int dx = __ldg(shift + n * 2 + 0) - PAD;  // width shift
    const int dy = __ldg(shift + n * 2 + 1) - PAD;  // height shift

    int ri = i + dy;
    ri = ri < 0 ? 0 : (ri > H - 1 ? H - 1 : ri);

    const float* __restrict__ row =
        x + ((size_t)(n * C + c) * H + ri) * W;

    const int j = j4 * 4;
    int c0 = j + 0 + dx; c0 = c0 < 0 ? 0 : (c0 > W - 1 ? W - 1 : c0);
    int c1 = j + 1 + dx; c1 = c1 < 0 ? 0 : (c1 > W - 1 ? W - 1 : c1);
    int c2 = j + 2 + dx; c2 = c2 < 0 ? 0 : (c2 > W - 1 ? W - 1 : c2);
    int c3 = j + 3 + dx; c3 = c3 < 0 ? 0 : (c3 > W - 1 ? W - 1 : c3);

    float4 v;
    v.x = __ldg(row + c0);
    v.y = __ldg(row + c1);
    v.z = __ldg(row + c2);
    v.w = __ldg(row + c3);

    reinterpret_cast<float4*>(out)[(size_t)n * PER_N + t] = v;
}

extern "C" void kernel_launch(void* const* d_in, const int* in_sizes, int n_in,
                              void* d_out, int out_size)
{
    const float* x     = (const float*)d_in[0];
    const int*   shift = (const int*)d_in[1];
    float*       out   = (float*)d_out;

    // PER_N = 112896 = 441 * 256
    dim3 grid(PER_N / 256, 128);
    shift_gather_kernel<<<grid, 256>>>(x, shift, out);
}